// round 6
// baseline (speedup 1.0000x reference)
#include <cuda_runtime.h>
#include <cuda_bf16.h>

// Shapes: query (N,T,C,L)=(32,64,256,64) fp32; key (T,N,C); out (T,N,C)
#define N_ 32
#define T_ 64
#define C_ 256
#define L_ 64
#define CH 4                       // n-values per chunk (16MB of q)
#define NCH (N_ / CH)              // 8 chunks

__device__ float g_part[N_ * T_ * L_];   // per-(n,t) partial scores
__device__ float g_probs[N_ * L_];       // softmax probs per n

// ---------------------------------------------------------------------------
// Pipelined role kernel. Kernel k in the chain runs three independent roles:
//   bid [0,256):    scores(chunk cs)   -- DRAM-bound  (q streamed into L2)
//   bid [256,260):  softmax(chunk cm)  -- tiny        (cm = cs-1, done prev k)
//   bid [260,516):  out(chunk co)      -- L2-bound    (co = cs-2, q resident)
// Dependencies are satisfied by kernel boundaries -> no spin, no atomics.
// ---------------------------------------------------------------------------
__global__ __launch_bounds__(256) void k_pipe(const float* __restrict__ q,
                                              const float* __restrict__ key,
                                              float* __restrict__ out,
                                              int cs, int cm, int co) {
    const int bid = blockIdx.x;
    const int tid = threadIdx.x;
    const int w = tid >> 5;
    const int lane = tid & 31;

    if (bid < CH * T_) {
        // ---------------- scores role (R4 k_scores body) ----------------
        if (cs < 0) return;
        const int n = cs * CH + (bid >> 6);
        const int t = bid & 63;
        const size_t b = (size_t)n * T_ + t;

        // warp's 32 key values preloaded, one per lane, broadcast via shfl
        const float kreg = key[((size_t)t * N_ + n) * C_ + (w << 5) + lane];
        const float2* __restrict__ qb = reinterpret_cast<const float2*>(q);
        const size_t rowbase = b * C_;

        float2 acc = make_float2(0.f, 0.f);
        #pragma unroll 8
        for (int i = 0; i < 32; ++i) {
            const float kv = __shfl_sync(0xffffffffu, kreg, i);
            const float2 qv = qb[(rowbase + (w << 5) + i) * 32 + lane];
            acc.x = fmaf(kv, qv.x, acc.x);
            acc.y = fmaf(kv, qv.y, acc.y);
        }
        __shared__ float2 sm[8][32];
        sm[w][lane] = acc;
        __syncthreads();
        if (w == 0) {
            float2 tot = sm[0][lane];
            #pragma unroll
            for (int j = 1; j < 8; ++j) {
                tot.x += sm[j][lane].x;
                tot.y += sm[j][lane].y;
            }
            reinterpret_cast<float2*>(g_part + b * L_)[lane] = tot;
        }
    } else if (bid < CH * T_ + CH) {
        // ---------------- softmax role ----------------
        if (cm < 0) return;
        const int n = cm * CH + (bid - CH * T_);
        __shared__ float s_red[4];

        float s = 0.f;
        if (tid < L_) {
            const float* __restrict__ p = g_part + (size_t)n * T_ * L_ + tid;
            #pragma unroll
            for (int t2 = 0; t2 < T_; ++t2) s += p[(size_t)t2 * L_];
            float m = s;
            #pragma unroll
            for (int off = 16; off; off >>= 1)
                m = fmaxf(m, __shfl_xor_sync(0xffffffffu, m, off));
            if (lane == 0) s_red[w] = m;
        }
        __syncthreads();
        float e = 0.f;
        if (tid < L_) {
            const float m = fmaxf(s_red[0], s_red[1]);
            e = __expf(s - m);
            float sum = e;
            #pragma unroll
            for (int off = 16; off; off >>= 1)
                sum += __shfl_xor_sync(0xffffffffu, sum, off);
            if (lane == 0) s_red[2 + w] = sum;
        }
        __syncthreads();
        if (tid < L_)
            g_probs[n * L_ + tid] = e / (s_red[2] + s_red[3]);
    } else {
        // ---------------- out role (R4 k_out body, L2-resident chunk) ----
        if (co < 0) return;
        const int b2 = bid - (CH * T_ + CH);
        const int n = co * CH + (b2 >> 6);
        const int t = b2 & 63;
        const int half = lane >> 4;
        const int l4 = lane & 15;

        const float4 pv = reinterpret_cast<const float4*>(g_probs + n * L_)[l4];
        const float4* __restrict__ qb = reinterpret_cast<const float4*>(q);
        const size_t rowbase = ((size_t)n * T_ + t) * C_;
        float* __restrict__ ob = out + ((size_t)t * N_ + n) * C_;

        #pragma unroll 8
        for (int i = 0; i < 16; ++i) {
            const int c = (w << 5) + (i << 1) + half;
            const float4 qv = qb[(rowbase + c) * 16 + l4];
            float v = fmaf(qv.x, pv.x,
                      fmaf(qv.y, pv.y,
                      fmaf(qv.z, pv.z, qv.w * pv.w)));
            #pragma unroll
            for (int off = 8; off; off >>= 1)
                v += __shfl_xor_sync(0xffffffffu, v, off);
            if (l4 == 0) ob[c] = v;
        }
    }
}

extern "C" void kernel_launch(void* const* d_in, const int* in_sizes, int n_in,
                              void* d_out, int out_size) {
    const float* q   = (const float*)d_in[0];
    const float* key = (const float*)d_in[1];
    float* out = (float*)d_out;

    const int GRID = CH * T_ + CH + CH * T_;   // 516 blocks
    for (int k = 0; k < NCH + 2; ++k) {
        const int cs = (k < NCH) ? k : -1;
        const int cm = (k >= 1 && k <= NCH) ? (k - 1) : -1;
        const int co = (k >= 2) ? (k - 2) : -1;
        k_pipe<<<GRID, 256>>>(q, key, out, cs, cm, co);
    }
}

// round 7
// speedup vs baseline: 1.5617x; 1.5617x over previous
#include <cuda_runtime.h>
#include <cuda_bf16.h>

// Shapes: query (N,T,C,L)=(32,64,256,64) fp32; key (T,N,C); out (T,N,C)
#define N_ 32
#define T_ 64
#define C_ 256
#define L_ 64

__device__ float g_part[N_ * T_ * L_];   // per-(n,t) partial scores
__device__ float g_probs[N_ * L_];       // softmax probs per n

// ---------------------------------------------------------------------------
// Kernel 1: partial scores. One block per (n,t)=b. 8 warps; each warp covers
// 32 c-rows as 16 iterations of 2 rows: half-warp per row, lane holds an
// l-quad (float4 -> LDG.128, 512B per warp per iter). Key values live in one
// register per lane (32 per warp) and are broadcast with a single shfl per
// row -> inner loop is 1 SHFL + 1 LDG.128 + 4 FMA per row-pair-half.
// __launch_bounds__(256,6) caps regs at 40 to hold ~48 warps/SM resident.
// ---------------------------------------------------------------------------
__global__ __launch_bounds__(256, 6) void k_scores(const float* __restrict__ q,
                                                   const float* __restrict__ key) {
    const int b = blockIdx.x;          // b = n*T_ + t
    const int n = b >> 6;
    const int t = b & 63;
    const int w = threadIdx.x >> 5;
    const int lane = threadIdx.x & 31;
    const int half = lane >> 4;        // which row of the pair
    const int l4 = lane & 15;          // float4 index within the 64-float row

    // Preload this warp's 32 key values: one per lane (coalesced 128B LDG).
    const float kreg = key[((size_t)t * N_ + n) * C_ + (w << 5) + lane];

    const float4* __restrict__ qb = reinterpret_cast<const float4*>(q);
    const size_t rowbase = (size_t)b * C_;   // rows of 16 float4

    float4 acc = make_float4(0.f, 0.f, 0.f, 0.f);
    #pragma unroll
    for (int i = 0; i < 16; ++i) {
        const int r = (i << 1) + half;                       // row within warp's 32
        const float kv = __shfl_sync(0xffffffffu, kreg, r);  // broadcast key[c]
        const float4 qv = qb[(rowbase + (w << 5) + r) * 16 + l4];
        acc.x = fmaf(kv, qv.x, acc.x);
        acc.y = fmaf(kv, qv.y, acc.y);
        acc.z = fmaf(kv, qv.z, acc.z);
        acc.w = fmaf(kv, qv.w, acc.w);
    }

    // combine the two halves of the warp (same l4, different rows)
    acc.x += __shfl_xor_sync(0xffffffffu, acc.x, 16);
    acc.y += __shfl_xor_sync(0xffffffffu, acc.y, 16);
    acc.z += __shfl_xor_sync(0xffffffffu, acc.z, 16);
    acc.w += __shfl_xor_sync(0xffffffffu, acc.w, 16);

    __shared__ float4 sm[8][16];
    if (half == 0) sm[w][l4] = acc;
    __syncthreads();

    if (threadIdx.x < 16) {
        float4 tot = sm[0][threadIdx.x];
        #pragma unroll
        for (int j = 1; j < 8; ++j) {
            const float4 v = sm[j][threadIdx.x];
            tot.x += v.x; tot.y += v.y; tot.z += v.z; tot.w += v.w;
        }
        reinterpret_cast<float4*>(g_part + (size_t)b * L_)[threadIdx.x] = tot;
    }
}

// ---------------------------------------------------------------------------
// Kernel 2: reduce partials over t, stable softmax over l. 32 blocks x 64 thr.
// ---------------------------------------------------------------------------
__global__ __launch_bounds__(64) void k_softmax() {
    const int n = blockIdx.x;
    const int l = threadIdx.x;

    float s = 0.f;
    const float* __restrict__ p = g_part + (size_t)n * T_ * L_ + l;
    #pragma unroll
    for (int t = 0; t < T_; ++t) s += p[(size_t)t * L_];

    float m = s;
    #pragma unroll
    for (int off = 16; off; off >>= 1)
        m = fmaxf(m, __shfl_xor_sync(0xffffffffu, m, off));
    __shared__ float wm[2];
    if ((l & 31) == 0) wm[l >> 5] = m;
    __syncthreads();
    m = fmaxf(wm[0], wm[1]);

    const float e = __expf(s - m);
    float sum = e;
    #pragma unroll
    for (int off = 16; off; off >>= 1)
        sum += __shfl_xor_sync(0xffffffffu, sum, off);
    __shared__ float ws[2];
    if ((l & 31) == 0) ws[l >> 5] = sum;
    __syncthreads();
    sum = ws[0] + ws[1];

    g_probs[n * L_ + l] = e / sum;
}

// ---------------------------------------------------------------------------
// Kernel 3: out[t,n,c] = sum_l q[n,t,c,l] * probs[n,l].
// REVERSED block mapping: k_scores streams q front-to-back, so the TAIL of q
// is still L2-resident (L2 ~126MB vs q 128MB). Read tail-first to hit it.
// (Unchanged — measured near the L2-bandwidth floor.)
// ---------------------------------------------------------------------------
__global__ __launch_bounds__(256) void k_out(const float* __restrict__ q,
                                             float* __restrict__ out) {
    const int b = (N_ * T_ - 1) - blockIdx.x;   // reverse order for L2 reuse
    const int n = b >> 6;
    const int t = b & 63;
    const int w = threadIdx.x >> 5;
    const int lane = threadIdx.x & 31;
    const int half = lane >> 4;
    const int l4 = lane & 15;

    const float4 pv = reinterpret_cast<const float4*>(g_probs + n * L_)[l4];
    const float4* __restrict__ qb = reinterpret_cast<const float4*>(q);
    const size_t rowbase = (size_t)b * C_;
    float* __restrict__ ob = out + ((size_t)t * N_ + n) * C_;

    #pragma unroll 8
    for (int i = 0; i < 16; ++i) {
        const int c = (w << 5) + (i << 1) + half;
        const float4 qv = qb[(rowbase + c) * 16 + l4];
        float v = fmaf(qv.x, pv.x, fmaf(qv.y, pv.y, fmaf(qv.z, pv.z, qv.w * pv.w)));
        #pragma unroll
        for (int off = 8; off; off >>= 1)
            v += __shfl_xor_sync(0xffffffffu, v, off);
        if (l4 == 0) ob[c] = v;
    }
}

extern "C" void kernel_launch(void* const* d_in, const int* in_sizes, int n_in,
                              void* d_out, int out_size) {
    const float* q   = (const float*)d_in[0];
    const float* key = (const float*)d_in[1];
    float* out = (float*)d_out;

    k_scores<<<N_ * T_, 256>>>(q, key);
    k_softmax<<<N_, 64>>>();
    k_out<<<N_ * T_, 256>>>(q, out);
}